// round 5
// baseline (speedup 1.0000x reference)
#include <cuda_runtime.h>
#include <math.h>

// Problem dims
#define T_STEPS 256
#define BATCH   256
#define OBSD    128
#define HIDD    256
#define HS      512
#define G4      2048
#define ACTD    16
#define TBROWS  (T_STEPS * BATCH)   // 65536
#define NCTA_SCAN 128

// ---------------- scratch (static device allocations; no cudaMalloc) ----------------
__device__ float g_feats[(size_t)TBROWS * HIDD];      // 64 MB
__device__ float g_xgp[(size_t)TBROWS * G4];          // 512 MB (gate-permuted x_gates)
__device__ float g_WiP[(size_t)HIDD * G4];            // 2 MB
__device__ float g_WhP[(size_t)HS * G4];              // 4 MB
__device__ float g_bP[G4];
__device__ float g_hs[(size_t)TBROWS * HS];           // 128 MB (h for every timestep)
__device__ unsigned g_cnt;                            // grid-barrier counter

__device__ __forceinline__ float sigmf(float x) { return 1.0f / (1.0f + expf(-x)); }
__device__ __forceinline__ float geluf(float v) {
    // jax.nn.gelu default (approximate=True, tanh form)
    float u = 0.7978845608028654f * (v + 0.044715f * v * v * v);
    return 0.5f * v * (1.0f + tanhf(u));
}

// ---------------- prep: gate-interleave permutation of Wi, Wh, b ----------------
// permuted column n' = 4*j + g  <->  original column g*512 + j   (i,f,g,o adjacent per unit)
__global__ void prep_kernel(const float* __restrict__ Wi,
                            const float* __restrict__ Wh,
                            const float* __restrict__ bl) {
    int stride = gridDim.x * blockDim.x;
    int idx = blockIdx.x * blockDim.x + threadIdx.x;
    for (int i = idx; i < HS * G4; i += stride) {
        int n = i & (G4 - 1);
        int k = i >> 11;
        g_WhP[i] = Wh[(size_t)k * G4 + (n & 3) * HS + (n >> 2)];
    }
    for (int i = idx; i < HIDD * G4; i += stride) {
        int n = i & (G4 - 1);
        int k = i >> 11;
        g_WiP[i] = Wi[(size_t)k * G4 + (n & 3) * HS + (n >> 2)];
    }
    for (int i = idx; i < G4; i += stride)
        g_bP[i] = bl[(i & 3) * HS + (i >> 2)];
    if (idx == 0) g_cnt = 0;   // reset grid barrier each launch/replay
}

// ---------------- generic fp32 tiled GEMM: C[M,N] = act(A[M,K] @ B[K,N] + bias) ----------------
// 64x64 tile per CTA, 256 threads, 4x4 accum per thread, K staged in 64-chunks.
template <bool GELU>
__global__ void __launch_bounds__(256) gemm64_kernel(
    const float* __restrict__ A, int lda,
    const float* __restrict__ B, int ldb,
    const float* __restrict__ bias,
    float* __restrict__ C, int ldc,
    int K)
{
    __shared__ float As[64 * 68];
    __shared__ float Bs[64 * 64];
    int nb = blockIdx.x, mb = blockIdx.y;
    int tid = threadIdx.x;
    int tn = tid & 15, tm = tid >> 4;

    float acc[4][4];
#pragma unroll
    for (int i = 0; i < 4; i++)
#pragma unroll
        for (int j = 0; j < 4; j++) acc[i][j] = 0.f;

    int nchunk = K >> 6;
    for (int kc = 0; kc < nchunk; kc++) {
        __syncthreads();
#pragma unroll
        for (int p = 0; p < 4; p++) {
            int idx = p * 256 + tid;
            int r = idx >> 4, c4 = (idx & 15) << 2;
            *(float4*)&As[r * 68 + c4] =
                *(const float4*)&A[(size_t)(mb * 64 + r) * lda + kc * 64 + c4];
            *(float4*)&Bs[r * 64 + c4] =
                *(const float4*)&B[(size_t)(kc * 64 + r) * ldb + nb * 64 + c4];
        }
        __syncthreads();
#pragma unroll 8
        for (int kk = 0; kk < 64; kk++) {
            float4 w = *(const float4*)&Bs[kk * 64 + tn * 4];
#pragma unroll
            for (int i = 0; i < 4; i++) {
                float a = As[(tm * 4 + i) * 68 + kk];
                acc[i][0] += a * w.x;
                acc[i][1] += a * w.y;
                acc[i][2] += a * w.z;
                acc[i][3] += a * w.w;
            }
        }
    }

    int n0 = nb * 64 + tn * 4;
    float4 bb = *(const float4*)&bias[n0];
#pragma unroll
    for (int i = 0; i < 4; i++) {
        int row = mb * 64 + tm * 4 + i;
        float4 o;
        o.x = acc[i][0] + bb.x; o.y = acc[i][1] + bb.y;
        o.z = acc[i][2] + bb.z; o.w = acc[i][3] + bb.w;
        if (GELU) { o.x = geluf(o.x); o.y = geluf(o.y); o.z = geluf(o.z); o.w = geluf(o.w); }
        *(float4*)&C[(size_t)row * ldc + n0] = o;
    }
}

// ---------------- persistent LSTM scan ----------------
// 128 CTAs (4 M-blocks x 32 N-blocks). Each CTA owns a 64-batch x 16-hidden-unit slice;
// its 4x4 accumulator columns are exactly (i,f,g,o) of one unit -> c stays in registers.
// One software grid barrier per timestep (all 128 CTAs resident: single wave).
__global__ void __launch_bounds__(256) scan_kernel() {
    __shared__ float Hs[64 * 68];
    __shared__ float Ws[64 * 64];
    int bid = blockIdx.x;
    int nb = bid & 31, mb = bid >> 5;
    int tid = threadIdx.x;
    int tn = tid & 15, tm = tid >> 4;
    int jj = nb * 16 + tn;               // hidden unit owned by this thread
    float c[4] = {0.f, 0.f, 0.f, 0.f};   // cell state for 4 batch rows (in registers!)

    for (int t = 0; t < T_STEPS; t++) {
        float acc[4][4];
#pragma unroll
        for (int i = 0; i < 4; i++)
#pragma unroll
            for (int j = 0; j < 4; j++) acc[i][j] = 0.f;

        if (t > 0) {
            const float* hprev = g_hs + (size_t)(t - 1) * BATCH * HS;
            for (int kc = 0; kc < 8; kc++) {
                __syncthreads();
#pragma unroll
                for (int p = 0; p < 4; p++) {
                    int idx = p * 256 + tid;
                    int r = idx >> 4, c4 = (idx & 15) << 2;
                    *(float4*)&Hs[r * 68 + c4] =
                        *(const float4*)&hprev[(size_t)(mb * 64 + r) * HS + kc * 64 + c4];
                    *(float4*)&Ws[r * 64 + c4] =
                        *(const float4*)&g_WhP[(size_t)(kc * 64 + r) * G4 + nb * 64 + c4];
                }
                __syncthreads();
#pragma unroll 8
                for (int kk = 0; kk < 64; kk++) {
                    float4 w = *(const float4*)&Ws[kk * 64 + tn * 4];
#pragma unroll
                    for (int i = 0; i < 4; i++) {
                        float a = Hs[(tm * 4 + i) * 68 + kk];
                        acc[i][0] += a * w.x;
                        acc[i][1] += a * w.y;
                        acc[i][2] += a * w.z;
                        acc[i][3] += a * w.w;
                    }
                }
            }
        }

        // gates -> cell update -> h (acc cols are i,f,g,o of unit jj)
        const float* xg = g_xgp + ((size_t)t * BATCH + mb * 64 + tm * 4) * G4 + nb * 64 + tn * 4;
        float* hout = g_hs + ((size_t)t * BATCH + mb * 64 + tm * 4) * HS + jj;
#pragma unroll
        for (int i = 0; i < 4; i++) {
            float4 xv = *(const float4*)(xg + (size_t)i * G4);
            float zi = acc[i][0] + xv.x;
            float zf = acc[i][1] + xv.y;
            float zg = acc[i][2] + xv.z;
            float zo = acc[i][3] + xv.w;
            float cn = sigmf(zf) * c[i] + sigmf(zi) * tanhf(zg);
            c[i] = cn;
            hout[(size_t)i * HS] = sigmf(zo) * tanhf(cn);
        }

        // ---- software grid barrier (release/acquire) ----
        __syncthreads();
        if (tid == 0) {
            __threadfence();                       // release all h stores to L2
            atomicAdd(&g_cnt, 1u);
            unsigned target = (unsigned)(t + 1) * NCTA_SCAN;
            unsigned v;
            do {
                asm volatile("ld.acquire.gpu.u32 %0, [%1];" : "=r"(v) : "l"(&g_cnt) : "memory");
            } while (v < target);
        }
        __syncthreads();
    }
}

// ---------------- heads: mu = hs@W_mu + b_mu, sigma = exp(log_std), value = hs@W_v + b_v ----------------
__global__ void __launch_bounds__(256) heads_kernel(
    const float* __restrict__ Wmu, const float* __restrict__ bmu,
    const float* __restrict__ lstd, const float* __restrict__ Wv,
    const float* __restrict__ bv, float* __restrict__ out)
{
    __shared__ float Wt[17 * HS];   // rows 0..15: W_mu^T, row 16: W_v
    __shared__ float sig_s[16];
    __shared__ float bias_s[17];
    int tid = threadIdx.x;
    for (int i = tid; i < HS * ACTD; i += 256) {
        int k = i >> 4, a = i & 15;
        Wt[a * HS + k] = Wmu[(size_t)k * ACTD + a];
    }
    for (int i = tid; i < HS; i += 256) Wt[16 * HS + i] = Wv[i];
    if (tid < 16) { sig_s[tid] = expf(lstd[tid]); bias_s[tid] = bmu[tid]; }
    if (tid == 16) bias_s[16] = bv[0];
    __syncthreads();

    int warp = tid >> 5, lane = tid & 31;
    int step = gridDim.x * 8;
    for (int row = blockIdx.x * 8 + warp; row < TBROWS; row += step) {
        const float* h = g_hs + (size_t)row * HS;
        float acc[17];
#pragma unroll
        for (int a = 0; a < 17; a++) acc[a] = 0.f;
#pragma unroll 4
        for (int q = 0; q < 16; q++) {
            float hv = h[q * 32 + lane];
#pragma unroll
            for (int a = 0; a < 17; a++) acc[a] += hv * Wt[a * HS + q * 32 + lane];
        }
#pragma unroll
        for (int a = 0; a < 17; a++) {
#pragma unroll
            for (int off = 16; off > 0; off >>= 1)
                acc[a] += __shfl_xor_sync(0xffffffffu, acc[a], off);
        }
        if (lane < 16) {
            out[(size_t)row * ACTD + lane] = acc[lane] + bias_s[lane];                    // mu
            out[(size_t)TBROWS * ACTD + (size_t)row * ACTD + lane] = sig_s[lane];         // sigma
        }
        if (lane == 0)
            out[(size_t)TBROWS * ACTD * 2 + row] = acc[16] + bias_s[16];                  // value
    }
}

// ---------------- launch ----------------
extern "C" void kernel_launch(void* const* d_in, const int* in_sizes, int n_in,
                              void* d_out, int out_size) {
    const float* x     = (const float*)d_in[0];
    const float* W_enc = (const float*)d_in[1];
    const float* b_enc = (const float*)d_in[2];
    const float* Wi    = (const float*)d_in[3];
    const float* Wh    = (const float*)d_in[4];
    const float* b_l   = (const float*)d_in[5];
    const float* W_mu  = (const float*)d_in[6];
    const float* b_mu  = (const float*)d_in[7];
    const float* lstd  = (const float*)d_in[8];
    const float* W_v   = (const float*)d_in[9];
    const float* b_v   = (const float*)d_in[10];
    float* out = (float*)d_out;

    float *feats, *xgp, *WiP, *bP;
    cudaGetSymbolAddress((void**)&feats, g_feats);
    cudaGetSymbolAddress((void**)&xgp,   g_xgp);
    cudaGetSymbolAddress((void**)&WiP,   g_WiP);
    cudaGetSymbolAddress((void**)&bP,    g_bP);

    // 1) permute weights into gate-interleaved layout + reset grid barrier
    prep_kernel<<<1024, 256>>>(Wi, Wh, b_l);

    // 2) encoder: feats = gelu(x @ W_enc + b_enc)   [65536 x 256]
    gemm64_kernel<true><<<dim3(HIDD / 64, TBROWS / 64), 256>>>(
        x, OBSD, W_enc, HIDD, b_enc, feats, HIDD, OBSD);

    // 3) x_gates (permuted): xgp = feats @ WiP + bP   [65536 x 2048]
    gemm64_kernel<false><<<dim3(G4 / 64, TBROWS / 64), 256>>>(
        feats, HIDD, WiP, G4, bP, xgp, G4, HIDD);

    // 4) sequential LSTM scan (persistent, one grid barrier per step)
    scan_kernel<<<NCTA_SCAN, 256>>>();

    // 5) heads
    heads_kernel<<<1024, 256>>>(W_mu, b_mu, lstd, W_v, b_v, out);
}

// round 6
// speedup vs baseline: 1.0089x; 1.0089x over previous
#include <cuda_runtime.h>
#include <math.h>

// Problem dims
#define T_STEPS 256
#define BATCH   256
#define OBSD    128
#define HIDD    256
#define HS      512
#define G4      2048
#define ACTD    16
#define TBROWS  (T_STEPS * BATCH)   // 65536
#define NCTA_SCAN 128

// ---------------- scratch (static device allocations; no cudaMalloc) ----------------
__device__ float g_feats[(size_t)TBROWS * HIDD];      // 64 MB
__device__ float g_xgp[(size_t)TBROWS * G4];          // 512 MB (gate-permuted x_gates)
__device__ float g_WiP[(size_t)HIDD * G4];            // 2 MB
__device__ float g_WhP[(size_t)HS * G4];              // 4 MB
__device__ float g_bP[G4];
__device__ float g_hs[(size_t)TBROWS * HS];           // 128 MB (h for every timestep)
__device__ unsigned g_cnt;                            // grid-barrier counter

__device__ __forceinline__ float sigmf(float x) { return 1.0f / (1.0f + expf(-x)); }
__device__ __forceinline__ float geluf(float v) {
    // jax.nn.gelu default (approximate=True, tanh form)
    float u = 0.7978845608028654f * (v + 0.044715f * v * v * v);
    return 0.5f * v * (1.0f + tanhf(u));
}

// ---------------- prep: gate-interleave permutation of Wi, Wh, b ----------------
// permuted column n' = 4*j + g  <->  original column g*512 + j   (i,f,g,o adjacent per unit)
__global__ void prep_kernel(const float* __restrict__ Wi,
                            const float* __restrict__ Wh,
                            const float* __restrict__ bl) {
    int stride = gridDim.x * blockDim.x;
    int idx = blockIdx.x * blockDim.x + threadIdx.x;
    for (int i = idx; i < HS * G4; i += stride) {
        int n = i & (G4 - 1);
        int k = i >> 11;
        g_WhP[i] = Wh[(size_t)k * G4 + (n & 3) * HS + (n >> 2)];
    }
    for (int i = idx; i < HIDD * G4; i += stride) {
        int n = i & (G4 - 1);
        int k = i >> 11;
        g_WiP[i] = Wi[(size_t)k * G4 + (n & 3) * HS + (n >> 2)];
    }
    for (int i = idx; i < G4; i += stride)
        g_bP[i] = bl[(i & 3) * HS + (i >> 2)];
    if (idx == 0) g_cnt = 0;   // reset grid barrier each launch/replay
}

// ---------------- generic fp32 tiled GEMM: C[M,N] = act(A[M,K] @ B[K,N] + bias) ----------------
// 64x64 tile per CTA, 256 threads, 4x4 accum per thread, K staged in 64-chunks.
template <bool GELU>
__global__ void __launch_bounds__(256) gemm64_kernel(
    const float* __restrict__ A, int lda,
    const float* __restrict__ B, int ldb,
    const float* __restrict__ bias,
    float* __restrict__ C, int ldc,
    int K)
{
    __shared__ float As[64 * 68];
    __shared__ float Bs[64 * 64];
    int nb = blockIdx.x, mb = blockIdx.y;
    int tid = threadIdx.x;
    int tn = tid & 15, tm = tid >> 4;

    float acc[4][4];
#pragma unroll
    for (int i = 0; i < 4; i++)
#pragma unroll
        for (int j = 0; j < 4; j++) acc[i][j] = 0.f;

    int nchunk = K >> 6;
    for (int kc = 0; kc < nchunk; kc++) {
        __syncthreads();
#pragma unroll
        for (int p = 0; p < 4; p++) {
            int idx = p * 256 + tid;
            int r = idx >> 4, c4 = (idx & 15) << 2;
            *(float4*)&As[r * 68 + c4] =
                *(const float4*)&A[(size_t)(mb * 64 + r) * lda + kc * 64 + c4];
            *(float4*)&Bs[r * 64 + c4] =
                *(const float4*)&B[(size_t)(kc * 64 + r) * ldb + nb * 64 + c4];
        }
        __syncthreads();
#pragma unroll 8
        for (int kk = 0; kk < 64; kk++) {
            float4 w = *(const float4*)&Bs[kk * 64 + tn * 4];
#pragma unroll
            for (int i = 0; i < 4; i++) {
                float a = As[(tm * 4 + i) * 68 + kk];
                acc[i][0] += a * w.x;
                acc[i][1] += a * w.y;
                acc[i][2] += a * w.z;
                acc[i][3] += a * w.w;
            }
        }
    }

    int n0 = nb * 64 + tn * 4;
    float4 bb = *(const float4*)&bias[n0];
#pragma unroll
    for (int i = 0; i < 4; i++) {
        int row = mb * 64 + tm * 4 + i;
        float4 o;
        o.x = acc[i][0] + bb.x; o.y = acc[i][1] + bb.y;
        o.z = acc[i][2] + bb.z; o.w = acc[i][3] + bb.w;
        if (GELU) { o.x = geluf(o.x); o.y = geluf(o.y); o.z = geluf(o.z); o.w = geluf(o.w); }
        *(float4*)&C[(size_t)row * ldc + n0] = o;
    }
}

// ---------------- persistent LSTM scan ----------------
// 128 CTAs (4 M-blocks x 32 N-blocks). Each CTA owns a 64-batch x 16-hidden-unit slice;
// its 4x4 accumulator columns are exactly (i,f,g,o) of one unit -> c stays in registers.
// One software grid barrier per timestep (all 128 CTAs resident: single wave).
__global__ void __launch_bounds__(256) scan_kernel() {
    __shared__ float Hs[64 * 68];
    __shared__ float Ws[64 * 64];
    int bid = blockIdx.x;
    int nb = bid & 31, mb = bid >> 5;
    int tid = threadIdx.x;
    int tn = tid & 15, tm = tid >> 4;
    int jj = nb * 16 + tn;               // hidden unit owned by this thread
    float c[4] = {0.f, 0.f, 0.f, 0.f};   // cell state for 4 batch rows (in registers!)

    for (int t = 0; t < T_STEPS; t++) {
        float acc[4][4];
#pragma unroll
        for (int i = 0; i < 4; i++)
#pragma unroll
            for (int j = 0; j < 4; j++) acc[i][j] = 0.f;

        if (t > 0) {
            const float* hprev = g_hs + (size_t)(t - 1) * BATCH * HS;
            for (int kc = 0; kc < 8; kc++) {
                __syncthreads();
#pragma unroll
                for (int p = 0; p < 4; p++) {
                    int idx = p * 256 + tid;
                    int r = idx >> 4, c4 = (idx & 15) << 2;
                    *(float4*)&Hs[r * 68 + c4] =
                        *(const float4*)&hprev[(size_t)(mb * 64 + r) * HS + kc * 64 + c4];
                    *(float4*)&Ws[r * 64 + c4] =
                        *(const float4*)&g_WhP[(size_t)(kc * 64 + r) * G4 + nb * 64 + c4];
                }
                __syncthreads();
#pragma unroll 8
                for (int kk = 0; kk < 64; kk++) {
                    float4 w = *(const float4*)&Ws[kk * 64 + tn * 4];
#pragma unroll
                    for (int i = 0; i < 4; i++) {
                        float a = Hs[(tm * 4 + i) * 68 + kk];
                        acc[i][0] += a * w.x;
                        acc[i][1] += a * w.y;
                        acc[i][2] += a * w.z;
                        acc[i][3] += a * w.w;
                    }
                }
            }
        }

        // gates -> cell update -> h (acc cols are i,f,g,o of unit jj)
        const float* xg = g_xgp + ((size_t)t * BATCH + mb * 64 + tm * 4) * G4 + nb * 64 + tn * 4;
        float* hout = g_hs + ((size_t)t * BATCH + mb * 64 + tm * 4) * HS + jj;
#pragma unroll
        for (int i = 0; i < 4; i++) {
            float4 xv = *(const float4*)(xg + (size_t)i * G4);
            float zi = acc[i][0] + xv.x;
            float zf = acc[i][1] + xv.y;
            float zg = acc[i][2] + xv.z;
            float zo = acc[i][3] + xv.w;
            float cn = sigmf(zf) * c[i] + sigmf(zi) * tanhf(zg);
            c[i] = cn;
            hout[(size_t)i * HS] = sigmf(zo) * tanhf(cn);
        }

        // ---- software grid barrier (release/acquire) ----
        __syncthreads();
        if (tid == 0) {
            __threadfence();                       // release all h stores to L2
            atomicAdd(&g_cnt, 1u);
            unsigned target = (unsigned)(t + 1) * NCTA_SCAN;
            unsigned v;
            do {
                asm volatile("ld.acquire.gpu.u32 %0, [%1];" : "=r"(v) : "l"(&g_cnt) : "memory");
            } while (v < target);
        }
        __syncthreads();
    }
}

// ---------------- heads: mu = hs@W_mu + b_mu, sigma = exp(log_std), value = hs@W_v + b_v ----------------
__global__ void __launch_bounds__(256) heads_kernel(
    const float* __restrict__ Wmu, const float* __restrict__ bmu,
    const float* __restrict__ lstd, const float* __restrict__ Wv,
    const float* __restrict__ bv, float* __restrict__ out)
{
    __shared__ float Wt[17 * HS];   // rows 0..15: W_mu^T, row 16: W_v
    __shared__ float sig_s[16];
    __shared__ float bias_s[17];
    int tid = threadIdx.x;
    for (int i = tid; i < HS * ACTD; i += 256) {
        int k = i >> 4, a = i & 15;
        Wt[a * HS + k] = Wmu[(size_t)k * ACTD + a];
    }
    for (int i = tid; i < HS; i += 256) Wt[16 * HS + i] = Wv[i];
    if (tid < 16) { sig_s[tid] = expf(lstd[tid]); bias_s[tid] = bmu[tid]; }
    if (tid == 16) bias_s[16] = bv[0];
    __syncthreads();

    int warp = tid >> 5, lane = tid & 31;
    int step = gridDim.x * 8;
    for (int row = blockIdx.x * 8 + warp; row < TBROWS; row += step) {
        const float* h = g_hs + (size_t)row * HS;
        float acc[17];
#pragma unroll
        for (int a = 0; a < 17; a++) acc[a] = 0.f;
#pragma unroll 4
        for (int q = 0; q < 16; q++) {
            float hv = h[q * 32 + lane];
#pragma unroll
            for (int a = 0; a < 17; a++) acc[a] += hv * Wt[a * HS + q * 32 + lane];
        }
#pragma unroll
        for (int a = 0; a < 17; a++) {
#pragma unroll
            for (int off = 16; off > 0; off >>= 1)
                acc[a] += __shfl_xor_sync(0xffffffffu, acc[a], off);
        }
        if (lane < 16) {
            out[(size_t)row * ACTD + lane] = acc[lane] + bias_s[lane];                    // mu
            out[(size_t)TBROWS * ACTD + (size_t)row * ACTD + lane] = sig_s[lane];         // sigma
        }
        if (lane == 0)
            out[(size_t)TBROWS * ACTD * 2 + row] = acc[16] + bias_s[16];                  // value
    }
}

// ---------------- launch ----------------
extern "C" void kernel_launch(void* const* d_in, const int* in_sizes, int n_in,
                              void* d_out, int out_size) {
    const float* x     = (const float*)d_in[0];
    const float* W_enc = (const float*)d_in[1];
    const float* b_enc = (const float*)d_in[2];
    const float* Wi    = (const float*)d_in[3];
    const float* Wh    = (const float*)d_in[4];
    const float* b_l   = (const float*)d_in[5];
    const float* W_mu  = (const float*)d_in[6];
    const float* b_mu  = (const float*)d_in[7];
    const float* lstd  = (const float*)d_in[8];
    const float* W_v   = (const float*)d_in[9];
    const float* b_v   = (const float*)d_in[10];
    float* out = (float*)d_out;

    float *feats, *xgp, *WiP, *bP;
    cudaGetSymbolAddress((void**)&feats, g_feats);
    cudaGetSymbolAddress((void**)&xgp,   g_xgp);
    cudaGetSymbolAddress((void**)&WiP,   g_WiP);
    cudaGetSymbolAddress((void**)&bP,    g_bP);

    // 1) permute weights into gate-interleaved layout + reset grid barrier
    prep_kernel<<<1024, 256>>>(Wi, Wh, b_l);

    // 2) encoder: feats = gelu(x @ W_enc + b_enc)   [65536 x 256]
    gemm64_kernel<true><<<dim3(HIDD / 64, TBROWS / 64), 256>>>(
        x, OBSD, W_enc, HIDD, b_enc, feats, HIDD, OBSD);

    // 3) x_gates (permuted): xgp = feats @ WiP + bP   [65536 x 2048]
    gemm64_kernel<false><<<dim3(G4 / 64, TBROWS / 64), 256>>>(
        feats, HIDD, WiP, G4, bP, xgp, G4, HIDD);

    // 4) sequential LSTM scan (persistent, one grid barrier per step)
    scan_kernel<<<NCTA_SCAN, 256>>>();

    // 5) heads
    heads_kernel<<<1024, 256>>>(W_mu, b_mu, lstd, W_v, b_v, out);
}

// round 8
// speedup vs baseline: 2.1555x; 2.1366x over previous
#include <cuda_runtime.h>
#include <cuda_bf16.h>
#include <math.h>
#include <stdint.h>

#define T_STEPS 256
#define BATCH   256
#define OBSD    128
#define HIDD    256
#define HS      512
#define G4      2048
#define ACTD    16
#define TBROWS  (T_STEPS * BATCH)
#define NCTA    128
typedef __nv_bfloat16 BF;

// ---------------- scratch (static device arrays; no cudaMalloc) ----------------
__device__ __align__(16) float g_xgp[(size_t)TBROWS * G4];   // permuted x_gates fp32
__device__ __align__(16) BF    g_fHi[(size_t)TBROWS * HIDD];
__device__ __align__(16) BF    g_fLo[(size_t)TBROWS * HIDD];
__device__ __align__(16) BF    g_hHi[(size_t)TBROWS * HS];
__device__ __align__(16) BF    g_hLo[(size_t)TBROWS * HS];
__device__ __align__(16) BF    g_WhHi[(size_t)G4 * HS];      // [n][k] permuted+transposed
__device__ __align__(16) BF    g_WhLo[(size_t)G4 * HS];
__device__ __align__(16) BF    g_WiHi[(size_t)G4 * HIDD];
__device__ __align__(16) BF    g_WiLo[(size_t)G4 * HIDD];
__device__ __align__(16) float g_bP[G4];
__device__ unsigned g_cnt;

__device__ __forceinline__ float sigmf(float x) { return 1.0f / (1.0f + expf(-x)); }
__device__ __forceinline__ float geluf(float v) {
    float u = 0.7978845608028654f * (v + 0.044715f * v * v * v);
    return 0.5f * v * (1.0f + tanhf(u));
}
__device__ __forceinline__ uint32_t smem_u32(const void* p) {
    uint32_t a;
    asm("{ .reg .u64 t; cvta.to.shared.u64 t, %1; cvt.u32.u64 %0, t; }" : "=r"(a) : "l"(p));
    return a;
}
__device__ __forceinline__ void ldmx4(uint32_t addr, uint32_t* r) {
    asm volatile("ldmatrix.sync.aligned.m8n8.x4.shared.b16 {%0,%1,%2,%3}, [%4];"
        : "=r"(r[0]), "=r"(r[1]), "=r"(r[2]), "=r"(r[3]) : "r"(addr));
}
__device__ __forceinline__ void mma16816(float* d, const uint32_t* a, const uint32_t* b) {
    asm volatile("mma.sync.aligned.m16n8k16.row.col.f32.bf16.bf16.f32 "
        "{%0,%1,%2,%3}, {%4,%5,%6,%7}, {%8,%9}, {%0,%1,%2,%3};"
        : "+f"(d[0]), "+f"(d[1]), "+f"(d[2]), "+f"(d[3])
        : "r"(a[0]), "r"(a[1]), "r"(a[2]), "r"(a[3]), "r"(b[0]), "r"(b[1]));
}

// strides (elems); byte strides ≡ 16 mod 128 -> conflict-free ldmatrix
#define AST 136
// ---- scan SMEM offsets (bytes) ----
#define S_OFF_C   0
#define S_OFF_G   4096
#define S_OFF_WHI 21504
#define S_OFF_WLO 88064
#define S_OFF_AHI 154624
#define S_OFF_ALO 189440
#define S_DYN     224256
#define WST_S     520
// ---- x_gates SMEM offsets ----
#define X_OFF_G   0
#define X_OFF_WHI 17408
#define X_OFF_WLO 51200
#define X_OFF_AHI 84992
#define X_OFF_ALO 119808
#define X_DYN     154624
#define WST_X     264
#define ABUF      17408   // bytes per A buffer (64 x 136 bf16)

// One K=128 chunk of MMAs: 8 k-steps x (2 mtiles x 2 ntiles x 3 passes)
template <int WST>
__device__ __forceinline__ void mma_chunk(uint32_t aHi, uint32_t aLo,
                                          uint32_t wHi, uint32_t wLo,
                                          int kbase, int lane, int wR, int wC,
                                          float acc[2][2][4]) {
#pragma unroll
    for (int ks = 0; ks < 8; ks++) {
        uint32_t bh[4], bl[4], afh[2][4], afl[2][4];
        int nrow = wC * 16 + (lane & 7) + (lane >> 4) * 8;
        int kcol = (kbase + ks) * 16 + ((lane >> 3) & 1) * 8;
        ldmx4(wHi + (nrow * WST + kcol) * 2, bh);
        ldmx4(wLo + (nrow * WST + kcol) * 2, bl);
#pragma unroll
        for (int mt = 0; mt < 2; mt++) {
            int row = wR * 32 + mt * 16 + (lane & 15);
            int col = ks * 16 + (lane >> 4) * 8;
            ldmx4(aHi + (row * AST + col) * 2, afh[mt]);
            ldmx4(aLo + (row * AST + col) * 2, afl[mt]);
        }
#pragma unroll
        for (int mt = 0; mt < 2; mt++)
#pragma unroll
            for (int nt = 0; nt < 2; nt++) {
                mma16816(acc[mt][nt], afh[mt], &bh[nt * 2]);
                mma16816(acc[mt][nt], afh[mt], &bl[nt * 2]);
                mma16816(acc[mt][nt], afl[mt], &bh[nt * 2]);
            }
    }
}

// ---------------- prep: permuted+transposed bf16-split weights ----------------
__global__ void prep_kernel(const float* __restrict__ Wi, const float* __restrict__ Wh,
                            const float* __restrict__ bl) {
    int stride = gridDim.x * blockDim.x;
    int idx = blockIdx.x * blockDim.x + threadIdx.x;
    for (int i = idx; i < G4 * HS; i += stride) {
        int n = i >> 9, k = i & (HS - 1);
        float v = Wh[(size_t)k * G4 + (n & 3) * HS + (n >> 2)];
        BF h = __float2bfloat16(v);
        g_WhHi[i] = h; g_WhLo[i] = __float2bfloat16(v - __bfloat162float(h));
    }
    for (int i = idx; i < G4 * HIDD; i += stride) {
        int n = i >> 8, k = i & (HIDD - 1);
        float v = Wi[(size_t)k * G4 + (n & 3) * HS + (n >> 2)];
        BF h = __float2bfloat16(v);
        g_WiHi[i] = h; g_WiLo[i] = __float2bfloat16(v - __bfloat162float(h));
    }
    for (int i = idx; i < G4; i += stride)
        g_bP[i] = bl[(i & 3) * HS + (i >> 2)];
    if (idx == 0) g_cnt = 0;
}

// ---------------- encoder: feats = gelu(x@W_enc + b), emitted bf16 hi/lo ----------------
__global__ void __launch_bounds__(256) enc_kernel(const float* __restrict__ A,
                                                  const float* __restrict__ B,
                                                  const float* __restrict__ bias) {
    __shared__ float As[64 * 68];
    __shared__ float Bs[64 * 64];
    int nb = blockIdx.x, mb = blockIdx.y, tid = threadIdx.x;
    int tn = tid & 15, tm = tid >> 4;
    float acc[4][4];
#pragma unroll
    for (int i = 0; i < 4; i++)
#pragma unroll
        for (int j = 0; j < 4; j++) acc[i][j] = 0.f;
    for (int kc = 0; kc < 2; kc++) {
        __syncthreads();
#pragma unroll
        for (int p = 0; p < 4; p++) {
            int idx = p * 256 + tid, r = idx >> 4, c4 = (idx & 15) << 2;
            *(float4*)&As[r * 68 + c4] = *(const float4*)&A[(size_t)(mb * 64 + r) * OBSD + kc * 64 + c4];
            *(float4*)&Bs[r * 64 + c4] = *(const float4*)&B[(size_t)(kc * 64 + r) * HIDD + nb * 64 + c4];
        }
        __syncthreads();
#pragma unroll 8
        for (int kk = 0; kk < 64; kk++) {
            float4 w = *(const float4*)&Bs[kk * 64 + tn * 4];
#pragma unroll
            for (int i = 0; i < 4; i++) {
                float a = As[(tm * 4 + i) * 68 + kk];
                acc[i][0] += a * w.x; acc[i][1] += a * w.y;
                acc[i][2] += a * w.z; acc[i][3] += a * w.w;
            }
        }
    }
    int n0 = nb * 64 + tn * 4;
    float4 bb = *(const float4*)&bias[n0];
#pragma unroll
    for (int i = 0; i < 4; i++) {
        int row = mb * 64 + tm * 4 + i;
        float v[4] = { geluf(acc[i][0] + bb.x), geluf(acc[i][1] + bb.y),
                       geluf(acc[i][2] + bb.z), geluf(acc[i][3] + bb.w) };
        __align__(8) BF hb[4], lb[4];
#pragma unroll
        for (int q = 0; q < 4; q++) {
            hb[q] = __float2bfloat16(v[q]);
            lb[q] = __float2bfloat16(v[q] - __bfloat162float(hb[q]));
        }
        *(int2*)(g_fHi + (size_t)row * HIDD + n0) = *(int2*)hb;
        *(int2*)(g_fLo + (size_t)row * HIDD + n0) = *(int2*)lb;
    }
}

// ---------------- x_gates: xgp = feats @ WiP + bP (bf16-split HMMA) ----------------
__global__ void __launch_bounds__(256) xg_mma_kernel() {
    extern __shared__ char sm[];
    float* gS = (float*)(sm + X_OFF_G);
    BF* Whi = (BF*)(sm + X_OFF_WHI);
    BF* Wlo = (BF*)(sm + X_OFF_WLO);
    uint32_t sb = smem_u32(sm);
    int tid = threadIdx.x, lane = tid & 31, wid = tid >> 5;
    int nb = blockIdx.x, my = blockIdx.y;
    int wR = wid >> 2, wC = wid & 3;

    // resident W slice [64][256] hi/lo
    {
        const BF* sh = g_WiHi + (size_t)(nb * 64) * HIDD;
        const BF* sl = g_WiLo + (size_t)(nb * 64) * HIDD;
        for (int i = tid; i < 2048; i += 256) {
            int r = i >> 5, c8 = (i & 31) * 8;
            *(int4*)&Whi[r * WST_X + c8] = *(const int4*)&sh[(size_t)r * HIDD + c8];
            *(int4*)&Wlo[r * WST_X + c8] = *(const int4*)&sl[(size_t)r * HIDD + c8];
        }
    }
    float acc[2][2][4];
#pragma unroll
    for (int a = 0; a < 2; a++)
#pragma unroll
        for (int b = 0; b < 2; b++)
#pragma unroll
            for (int e = 0; e < 4; e++) acc[a][b][e] = 0.f;

    const BF* Ah = g_fHi + (size_t)(my * 64) * HIDD;
    const BF* Al = g_fLo + (size_t)(my * 64) * HIDD;
    int4 ph[4], pl[4];
#pragma unroll
    for (int p = 0; p < 4; p++) {
        int idx = tid + p * 256, r = idx >> 4, c8 = (idx & 15) * 8;
        ph[p] = *(const int4*)&Ah[(size_t)r * HIDD + c8];
        pl[p] = *(const int4*)&Al[(size_t)r * HIDD + c8];
    }
    __syncthreads();
#pragma unroll
    for (int ch = 0; ch < 2; ch++) {
        BF* bh = (BF*)(sm + X_OFF_AHI + (ch & 1) * ABUF);
        BF* bl = (BF*)(sm + X_OFF_ALO + (ch & 1) * ABUF);
#pragma unroll
        for (int p = 0; p < 4; p++) {
            int idx = tid + p * 256, r = idx >> 4, c8 = (idx & 15) * 8;
            *(int4*)&bh[r * AST + c8] = ph[p];
            *(int4*)&bl[r * AST + c8] = pl[p];
        }
        __syncthreads();
        if (ch < 1) {
#pragma unroll
            for (int p = 0; p < 4; p++) {
                int idx = tid + p * 256, r = idx >> 4, c8 = (idx & 15) * 8;
                ph[p] = *(const int4*)&Ah[(size_t)r * HIDD + 128 + c8];
                pl[p] = *(const int4*)&Al[(size_t)r * HIDD + 128 + c8];
            }
        }
        mma_chunk<WST_X>(sb + X_OFF_AHI + (ch & 1) * ABUF, sb + X_OFF_ALO + (ch & 1) * ABUF,
                         sb + X_OFF_WHI, sb + X_OFF_WLO, ch * 8, lane, wR, wC, acc);
        __syncthreads();
    }
    // accums -> gS
#pragma unroll
    for (int mt = 0; mt < 2; mt++)
#pragma unroll
        for (int nt = 0; nt < 2; nt++)
#pragma unroll
            for (int e = 0; e < 4; e++) {
                int row = wR * 32 + mt * 16 + (lane >> 2) + (e >> 1) * 8;
                int col = wC * 16 + nt * 8 + (lane & 3) * 2 + (e & 1);
                gS[row * 68 + col] = acc[mt][nt][e];
            }
    __syncthreads();
    int erow = tid >> 2, eu4 = tid & 3;
    float* gr = &gS[erow * 68 + eu4 * 16];
    int col0 = nb * 64 + eu4 * 16;
    float* op = g_xgp + ((size_t)my * 64 + erow) * G4 + col0;
#pragma unroll
    for (int q = 0; q < 4; q++) {
        float4 bb = *(const float4*)&g_bP[col0 + q * 4];
        float4 o;
        o.x = gr[q * 4 + 0] + bb.x; o.y = gr[q * 4 + 1] + bb.y;
        o.z = gr[q * 4 + 2] + bb.z; o.w = gr[q * 4 + 3] + bb.w;
        *(float4*)(op + q * 4) = o;
    }
}

// ---------------- persistent HMMA LSTM scan ----------------
// 128 CTAs = 4 M-tiles(64 batch) x 32 N-tiles(64 gate cols = 16 units).
__global__ void __launch_bounds__(256) scan_mma_kernel() {
    extern __shared__ char sm[];
    float* cS = (float*)(sm + S_OFF_C);
    float* gS = (float*)(sm + S_OFF_G);
    BF* Whi = (BF*)(sm + S_OFF_WHI);
    BF* Wlo = (BF*)(sm + S_OFF_WLO);
    uint32_t sb = smem_u32(sm);
    int tid = threadIdx.x, lane = tid & 31, wid = tid >> 5;
    int mb = blockIdx.x >> 5, nb = blockIdx.x & 31;
    int wR = wid >> 2, wC = wid & 3;

    // resident Wh slice [64][512] hi/lo (130 KB)
    {
        const BF* sh = g_WhHi + (size_t)(nb * 64) * HS;
        const BF* sl = g_WhLo + (size_t)(nb * 64) * HS;
        for (int i = tid; i < 4096; i += 256) {
            int r = i >> 6, c8 = (i & 63) * 8;
            *(int4*)&Whi[r * WST_S + c8] = *(const int4*)&sh[(size_t)r * HS + c8];
            *(int4*)&Wlo[r * WST_S + c8] = *(const int4*)&sl[(size_t)r * HS + c8];
        }
    }
    for (int i = tid; i < 64 * 16; i += 256) cS[i] = 0.f;
    __syncthreads();

    int erow = tid >> 2, eu4 = tid & 3;

    for (int t = 0; t < T_STEPS; t++) {
        // prefetch this thread's gate inputs
        const float* xgp = g_xgp + ((size_t)t * BATCH + mb * 64 + erow) * G4 + nb * 64 + eu4 * 16;
        float xr[16];
        *(float4*)&xr[0]  = *(const float4*)(xgp + 0);
        *(float4*)&xr[4]  = *(const float4*)(xgp + 4);
        *(float4*)&xr[8]  = *(const float4*)(xgp + 8);
        *(float4*)&xr[12] = *(const float4*)(xgp + 12);

        float acc[2][2][4];
#pragma unroll
        for (int a = 0; a < 2; a++)
#pragma unroll
            for (int b = 0; b < 2; b++)
#pragma unroll
                for (int e = 0; e < 4; e++) acc[a][b][e] = 0.f;

        if (t > 0) {
            const BF* Ah = g_hHi + ((size_t)(t - 1) * BATCH + mb * 64) * HS;
            const BF* Al = g_hLo + ((size_t)(t - 1) * BATCH + mb * 64) * HS;
            int4 ph[4], pl[4];
#pragma unroll
            for (int p = 0; p < 4; p++) {
                int idx = tid + p * 256, r = idx >> 4, c8 = (idx & 15) * 8;
                ph[p] = *(const int4*)&Ah[(size_t)r * HS + c8];
                pl[p] = *(const int4*)&Al[(size_t)r * HS + c8];
            }
#pragma unroll 1
            for (int ch = 0; ch < 4; ch++) {
                BF* bh = (BF*)(sm + S_OFF_AHI + (ch & 1) * ABUF);
                BF* bl = (BF*)(sm + S_OFF_ALO + (ch & 1) * ABUF);
#pragma unroll
                for (int p = 0; p < 4; p++) {
                    int idx = tid + p * 256, r = idx >> 4, c8 = (idx & 15) * 8;
                    *(int4*)&bh[r * AST + c8] = ph[p];
                    *(int4*)&bl[r * AST + c8] = pl[p];
                }
                __syncthreads();
                if (ch < 3) {
#pragma unroll
                    for (int p = 0; p < 4; p++) {
                        int idx = tid + p * 256, r = idx >> 4, c8 = (idx & 15) * 8;
                        ph[p] = *(const int4*)&Ah[(size_t)r * HS + (ch + 1) * 128 + c8];
                        pl[p] = *(const int4*)&Al[(size_t)r * HS + (ch + 1) * 128 + c8];
                    }
                }
                mma_chunk<WST_S>(sb + S_OFF_AHI + (ch & 1) * ABUF, sb + S_OFF_ALO + (ch & 1) * ABUF,
                                 sb + S_OFF_WHI, sb + S_OFF_WLO, ch * 8, lane, wR, wC, acc);
                __syncthreads();
            }
        }

        // accums -> gate smem
#pragma unroll
        for (int mt = 0; mt < 2; mt++)
#pragma unroll
            for (int nt = 0; nt < 2; nt++)
#pragma unroll
                for (int e = 0; e < 4; e++) {
                    int row = wR * 32 + mt * 16 + (lane >> 2) + (e >> 1) * 8;
                    int col = wC * 16 + nt * 8 + (lane & 3) * 2 + (e & 1);
                    gS[row * 68 + col] = acc[mt][nt][e];
                }
        __syncthreads();

        // epilogue: 4 units per thread, c in SMEM (thread-exclusive slot)
        float* gr = &gS[erow * 68 + eu4 * 16];
        float* cp = &cS[erow * 16 + eu4 * 4];
        __align__(8) BF hb[4], lb[4];
#pragma unroll
        for (int q = 0; q < 4; q++) {
            float zi = gr[q * 4 + 0] + xr[q * 4 + 0];
            float zf = gr[q * 4 + 1] + xr[q * 4 + 1];
            float zg = gr[q * 4 + 2] + xr[q * 4 + 2];
            float zo = gr[q * 4 + 3] + xr[q * 4 + 3];
            float cn = sigmf(zf) * cp[q] + sigmf(zi) * tanhf(zg);
            cp[q] = cn;
            float hv = sigmf(zo) * tanhf(cn);
            BF hh = __float2bfloat16(hv);
            hb[q] = hh;
            lb[q] = __float2bfloat16(hv - __bfloat162float(hh));
        }
        size_t ho = ((size_t)t * BATCH + mb * 64 + erow) * HS + nb * 16 + eu4 * 4;
        *(int2*)&g_hHi[ho] = *(int2*)hb;
        *(int2*)&g_hLo[ho] = *(int2*)lb;

        // grid barrier (release h(t); all 128 CTAs single-wave)
        __syncthreads();
        if (tid == 0) {
            __threadfence();
            atomicAdd(&g_cnt, 1u);
            unsigned target = (unsigned)(t + 1) * NCTA, v;
            do {
                asm volatile("ld.acquire.gpu.u32 %0, [%1];" : "=r"(v) : "l"(&g_cnt) : "memory");
            } while (v < target);
        }
        __syncthreads();
    }
}

// ---------------- heads ----------------
__global__ void __launch_bounds__(256) heads_kernel(
    const float* __restrict__ Wmu, const float* __restrict__ bmu,
    const float* __restrict__ lstd, const float* __restrict__ Wv,
    const float* __restrict__ bv, float* __restrict__ out) {
    __shared__ float Wt[17 * HS];
    __shared__ float sig_s[16], bias_s[17];
    int tid = threadIdx.x;
    for (int i = tid; i < HS * ACTD; i += 256) {
        int k = i >> 4, a = i & 15;
        Wt[a * HS + k] = Wmu[(size_t)k * ACTD + a];
    }
    for (int i = tid; i < HS; i += 256) Wt[16 * HS + i] = Wv[i];
    if (tid < 16) { sig_s[tid] = expf(lstd[tid]); bias_s[tid] = bmu[tid]; }
    if (tid == 16) bias_s[16] = bv[0];
    __syncthreads();

    int warp = tid >> 5, lane = tid & 31;
    int step = gridDim.x * 8;
    for (int row = blockIdx.x * 8 + warp; row < TBROWS; row += step) {
        const BF* hh = g_hHi + (size_t)row * HS;
        const BF* hl = g_hLo + (size_t)row * HS;
        float acc[17];
#pragma unroll
        for (int a = 0; a < 17; a++) acc[a] = 0.f;
#pragma unroll 4
        for (int q = 0; q < 16; q++) {
            int idx = q * 32 + lane;
            float hv = __bfloat162float(hh[idx]) + __bfloat162float(hl[idx]);
#pragma unroll
            for (int a = 0; a < 17; a++) acc[a] += hv * Wt[a * HS + idx];
        }
#pragma unroll
        for (int a = 0; a < 17; a++)
#pragma unroll
            for (int off = 16; off > 0; off >>= 1)
                acc[a] += __shfl_xor_sync(0xffffffffu, acc[a], off);
        if (lane < 16) {
            out[(size_t)row * ACTD + lane] = acc[lane] + bias_s[lane];
            out[(size_t)TBROWS * ACTD + (size_t)row * ACTD + lane] = sig_s[lane];
        }
        if (lane == 0)
            out[(size_t)TBROWS * ACTD * 2 + row] = acc[16] + bias_s[16];
    }
}

// ---------------- launch ----------------
extern "C" void kernel_launch(void* const* d_in, const int* in_sizes, int n_in,
                              void* d_out, int out_size) {
    const float* x     = (const float*)d_in[0];
    const float* W_enc = (const float*)d_in[1];
    const float* b_enc = (const float*)d_in[2];
    const float* Wi    = (const float*)d_in[3];
    const float* Wh    = (const float*)d_in[4];
    const float* b_l   = (const float*)d_in[5];
    const float* W_mu  = (const float*)d_in[6];
    const float* b_mu  = (const float*)d_in[7];
    const float* lstd  = (const float*)d_in[8];
    const float* W_v   = (const float*)d_in[9];
    const float* b_v   = (const float*)d_in[10];
    float* out = (float*)d_out;

    cudaFuncSetAttribute(xg_mma_kernel,   cudaFuncAttributeMaxDynamicSharedMemorySize, X_DYN);
    cudaFuncSetAttribute(scan_mma_kernel, cudaFuncAttributeMaxDynamicSharedMemorySize, S_DYN);

    prep_kernel<<<1024, 256>>>(Wi, Wh, b_l);
    enc_kernel<<<dim3(HIDD / 64, TBROWS / 64), 256>>>(x, W_enc, b_enc);
    xg_mma_kernel<<<dim3(32, TBROWS / 64), 256, X_DYN>>>();
    scan_mma_kernel<<<NCTA, 256, S_DYN>>>();
    heads_kernel<<<1024, 256>>>(W_mu, b_mu, lstd, W_v, b_v, out);
}